// round 1
// baseline (speedup 1.0000x reference)
#include <cuda_runtime.h>
#include <cuda_bf16.h>

#define BB 4
#define NN 256
#define HH 256
#define WW 256
#define HW 65536   // HH*WW

// Scratch (device globals — no allocations allowed)
__device__ int    g_cidx[BB * NN];    // flat center index within HxW for each (b,n)
__device__ float  g_scale[BB * NN];   // 0.0f if pad_mask[b,n] else 1.0f
__device__ double g_acc;              // global sum accumulator

// ---------------------------------------------------------------------------
// Kernel 0: reset accumulator (must be re-run every launch: deterministic)
// ---------------------------------------------------------------------------
__global__ void k_init() { g_acc = 0.0; }

// ---------------------------------------------------------------------------
// Kernel 1: find the (unique) center per (b,n) channel and stash pad scale.
// One block per (b,n); 256 threads scan 65536 ints with int4 loads.
// ---------------------------------------------------------------------------
__global__ __launch_bounds__(256) void k_centers(const int* __restrict__ tc,
                                                 const int* __restrict__ pad) {
    const int bn  = blockIdx.x;
    const int tid = threadIdx.x;
    if (tid == 0) g_scale[bn] = pad[bn] ? 0.0f : 1.0f;

    const int4* p = reinterpret_cast<const int4*>(tc) + (size_t)bn * (HW / 4);
    #pragma unroll 8
    for (int i = 0; i < 64; i++) {
        const int idx4 = i * 256 + tid;          // coalesced: warp reads 512B
        const int4 v  = __ldg(&p[idx4]);
        if (v.x | v.y | v.z | v.w) {             // rare: exactly one per block
            const int off = v.x ? 0 : (v.y ? 1 : (v.z ? 2 : 3));
            g_cidx[bn] = idx4 * 4 + off;
        }
    }
}

// ---------------------------------------------------------------------------
// Kernel 2: main fused pass. One block per (b,h) row; thread = w.
// Per-n center data cached in shared memory; inner loop over n with
// coalesced 128B-per-warp loads from targets.
// ---------------------------------------------------------------------------
__global__ __launch_bounds__(256) void k_main(const float* __restrict__ pred,
                                              const int*   __restrict__ tgt) {
    __shared__ float s_dr2[NN];   // (h - cr)^2 as float
    __shared__ int   s_cc [NN];   // center column
    __shared__ float s_sc [NN];   // pad scale (0 or 1)

    const int b = blockIdx.x >> 8;     // grid = BB*HH = 1024
    const int h = blockIdx.x & 255;
    const int w = threadIdx.x;

    {
        const int n  = threadIdx.x;
        const int ci = g_cidx[b * NN + n];
        const int cr = ci >> 8;        // WW == 256
        const int cc = ci & 255;
        const float dr = (float)(h - cr);
        s_dr2[n] = dr * dr;
        s_cc [n] = cc;
        s_sc [n] = g_scale[b * NN + n];
    }
    __syncthreads();

    const int* tp = tgt + (size_t)b * NN * HW + (size_t)h * WW + w;

    float imp = 0.0f;
    int   ts  = 0;
    #pragma unroll 8
    for (int n = 0; n < NN; n++) {
        const int t  = __ldg(tp + (size_t)n * HW);   // coalesced per warp
        const int dc = w - s_cc[n];
        const float d2 = s_dr2[n] + (float)(dc * dc) + 1e-6f;
        ts  += t;
        imp += ((float)t * s_sc[n]) / d2;            // numerator 0 when t==0
    }

    // importance_coeff = ~tsum * 0.5  (bitwise invert: -ts-1)
    const float coeff = (float)(~ts) * 0.5f;
    const float pi    = imp + coeff;

    const float x = pred[((size_t)b * HH + h) * WW + w];
    const float z = (float)ts;
    // stable BCE-with-logits
    const float bce = fmaxf(x, 0.0f) - x * z + log1pf(expf(-fabsf(x)));

    double v = (double)(bce * pi);

    // warp reduce (double)
    #pragma unroll
    for (int off = 16; off; off >>= 1)
        v += __shfl_down_sync(0xffffffffu, v, off);

    __shared__ double s_red[8];
    const int lane = threadIdx.x & 31;
    const int wid  = threadIdx.x >> 5;
    if (lane == 0) s_red[wid] = v;
    __syncthreads();
    if (wid == 0) {
        v = (lane < 8) ? s_red[lane] : 0.0;
        #pragma unroll
        for (int off = 4; off; off >>= 1)
            v += __shfl_down_sync(0xffu, v, off);
        if (lane == 0) atomicAdd(&g_acc, v);
    }
}

// ---------------------------------------------------------------------------
// Kernel 3: finalize mean
// ---------------------------------------------------------------------------
__global__ void k_final(float* out) {
    out[0] = (float)(g_acc * (1.0 / (double)(BB * HW)));
}

// ---------------------------------------------------------------------------
// Launch contract
// inputs (metadata order): predictions f32[4,256,256], target_centers i32[4,256,256,256],
//                          targets i32[4,256,256,256], pad_mask (bool->int32)[4,256]
// output: f32 scalar
// ---------------------------------------------------------------------------
extern "C" void kernel_launch(void* const* d_in, const int* in_sizes, int n_in,
                              void* d_out, int out_size) {
    const float* pred = (const float*)d_in[0];
    const int*   tc   = (const int*)d_in[1];
    const int*   tgt  = (const int*)d_in[2];
    const int*   pad  = (const int*)d_in[3];
    float* out = (float*)d_out;

    k_init<<<1, 1>>>();
    k_centers<<<BB * NN, 256>>>(tc, pad);
    k_main<<<BB * HH, 256>>>(pred, tgt);
    k_final<<<1, 1>>>(out);
}

// round 2
// speedup vs baseline: 2.1493x; 2.1493x over previous
#include <cuda_runtime.h>
#include <cuda_bf16.h>

#define BB 4
#define NN 256
#define HH 256
#define WW 256
#define HW 65536   // HH*WW

// Scratch (device globals — no allocations allowed)
__device__ int      g_cidx[BB * NN];    // flat center index within HxW for each (b,n)
__device__ float    g_scale[BB * NN];   // 0.0f if pad_mask[b,n] else 1.0f
__device__ double   g_acc;              // global sum accumulator
__device__ unsigned g_cnt;              // blocks-done counter for last-block finalize

// ---------------------------------------------------------------------------
// Kernel 1: find the (unique) center per (b,n), stash pad scale, reset acc.
// One block per (b,n); 256 threads scan 65536 ints with int4 streaming loads.
// ---------------------------------------------------------------------------
__global__ __launch_bounds__(256) void k_centers(const int* __restrict__ tc,
                                                 const int* __restrict__ pad) {
    const int bn  = blockIdx.x;
    const int tid = threadIdx.x;
    if (bn == 0 && tid == 0) { g_acc = 0.0; g_cnt = 0u; }
    if (tid == 0) g_scale[bn] = pad[bn] ? 0.0f : 1.0f;

    const int4* p = reinterpret_cast<const int4*>(tc) + (size_t)bn * (HW / 4);
    #pragma unroll 8
    for (int i = 0; i < 64; i++) {
        const int idx4 = i * 256 + tid;          // coalesced: warp reads 512B
        const int4 v  = __ldcs(&p[idx4]);        // streaming: no reuse
        if (v.x | v.y | v.z | v.w) {             // rare: exactly one hit per block
            const int off = v.x ? 0 : (v.y ? 1 : (v.z ? 2 : 3));
            g_cidx[bn] = idx4 * 4 + off;
        }
    }
}

// ---------------------------------------------------------------------------
// Kernel 2: main fused pass + finalize.
// One block per (b,h) row; 256 threads = 4 n-partitions x 64 w-quads.
// Each thread processes 4 consecutive w pixels (int4 loads) over 64 n values.
// Cross-partition reduction in smem, then BCE + block/grid double reduction.
// Last block writes the mean.
// ---------------------------------------------------------------------------
__global__ __launch_bounds__(256) void k_main(const float* __restrict__ pred,
                                              const int*   __restrict__ tgt,
                                              float*       __restrict__ out) {
    __shared__ float s_dr2[NN];      // (h-cr)^2 + 1e-6
    __shared__ int   s_cc [NN];
    __shared__ float s_sc [NN];
    __shared__ float s_imp[4][WW];   // per-partition importance partials
    __shared__ int   s_ts [4][WW];   // per-partition target-sum partials

    const int b   = blockIdx.x >> 8;   // grid = BB*HH = 1024
    const int h   = blockIdx.x & 255;
    const int tid = threadIdx.x;

    {
        const int n  = tid;
        const int ci = g_cidx[b * NN + n];
        const int cr = ci >> 8;          // WW == 256
        const int cc = ci & 255;
        const float dr = (float)(h - cr);
        s_dr2[n] = dr * dr + 1e-6f;
        s_cc [n] = cc;
        s_sc [n] = g_scale[b * NN + n];
    }
    __syncthreads();

    const int q    = tid & 63;          // w-quad index
    const int part = tid >> 6;          // n partition 0..3
    const int w0   = q * 4;

    const int4* tp = reinterpret_cast<const int4*>(
                         tgt + (size_t)b * NN * HW + (size_t)h * WW) + q;

    float imp0 = 0.f, imp1 = 0.f, imp2 = 0.f, imp3 = 0.f;
    int   ts0 = 0, ts1 = 0, ts2 = 0, ts3 = 0;

    #pragma unroll 8
    for (int j = 0; j < 64; j++) {
        const int n = part * 64 + j;
        const int4 t = __ldcs(tp + (size_t)n * (HW / 4));  // 512B/warp, streaming
        const float dr2 = s_dr2[n];
        const int   cc  = s_cc[n];
        const float sc  = s_sc[n];
        int dc;
        dc = w0     - cc; imp0 += __fdividef((float)t.x * sc, dr2 + (float)(dc * dc)); ts0 += t.x;
        dc = w0 + 1 - cc; imp1 += __fdividef((float)t.y * sc, dr2 + (float)(dc * dc)); ts1 += t.y;
        dc = w0 + 2 - cc; imp2 += __fdividef((float)t.z * sc, dr2 + (float)(dc * dc)); ts2 += t.z;
        dc = w0 + 3 - cc; imp3 += __fdividef((float)t.w * sc, dr2 + (float)(dc * dc)); ts3 += t.w;
    }

    // vector stores of partials (16B-aligned: w0 = 4q)
    *reinterpret_cast<float4*>(&s_imp[part][w0]) = make_float4(imp0, imp1, imp2, imp3);
    *reinterpret_cast<int4*>  (&s_ts [part][w0]) = make_int4 (ts0, ts1, ts2, ts3);
    __syncthreads();

    // thread tid now owns pixel w = tid
    const int w = tid;
    const float imp = s_imp[0][w] + s_imp[1][w] + s_imp[2][w] + s_imp[3][w];
    const int   ts  = s_ts [0][w] + s_ts [1][w] + s_ts [2][w] + s_ts [3][w];

    // importance_coeff = ~tsum * 0.5  (bitwise invert: -ts-1)
    const float pi = imp + (float)(~ts) * 0.5f;

    const float x = pred[((size_t)b * HH + h) * WW + w];
    const float z = (float)ts;
    const float bce = fmaxf(x, 0.0f) - x * z + log1pf(expf(-fabsf(x)));

    double v = (double)(bce * pi);

    // warp reduce (double)
    #pragma unroll
    for (int off = 16; off; off >>= 1)
        v += __shfl_down_sync(0xffffffffu, v, off);

    __shared__ double s_red[8];
    const int lane = tid & 31;
    const int wid  = tid >> 5;
    if (lane == 0) s_red[wid] = v;
    __syncthreads();
    if (wid == 0) {
        v = (lane < 8) ? s_red[lane] : 0.0;
        #pragma unroll
        for (int off = 4; off; off >>= 1)
            v += __shfl_down_sync(0xffu, v, off);
        if (lane == 0) {
            atomicAdd(&g_acc, v);
            __threadfence();
            const unsigned done = atomicAdd(&g_cnt, 1u);
            if (done == (unsigned)gridDim.x - 1u) {
                const double total = atomicAdd(&g_acc, 0.0);  // coherent read
                out[0] = (float)(total * (1.0 / (double)(BB * HW)));
            }
        }
    }
}

// ---------------------------------------------------------------------------
// Launch contract
// inputs (metadata order): predictions f32[4,256,256], target_centers i32[4,256,256,256],
//                          targets i32[4,256,256,256], pad_mask (bool->int32)[4,256]
// output: f32 scalar
// ---------------------------------------------------------------------------
extern "C" void kernel_launch(void* const* d_in, const int* in_sizes, int n_in,
                              void* d_out, int out_size) {
    const float* pred = (const float*)d_in[0];
    const int*   tc   = (const int*)d_in[1];
    const int*   tgt  = (const int*)d_in[2];
    const int*   pad  = (const int*)d_in[3];
    float* out = (float*)d_out;

    k_centers<<<BB * NN, 256>>>(tc, pad);
    k_main<<<BB * HH, 256>>>(pred, tgt, out);
}